// round 1
// baseline (speedup 1.0000x reference)
#include <cuda_runtime.h>

// Problem constants (SimpleSSM): x [8, 4096, 1024] fp32, per-channel diagonal SSM + LayerNorm(dim=-1)
constexpr int NB = 8;      // batch
constexpr int NT = 4096;   // sequence length
constexpr int ND = 1024;   // model dim (channels)
constexpr int LCH = 64;    // chunk length (timesteps per chunk)
constexpr int NCHUNK = NT / LCH;   // 64 chunks
constexpr float EPS = 1e-5f;

static_assert(LCH == 64, "k_scan hardcodes A^64 via 6 squarings");
static_assert(ND % 4 == 0, "float4 vectorization");

// Scratch (allocation-free rule: __device__ globals). 2 MB each.
__device__ float g_S[(size_t)NB * NCHUNK * ND];  // per-chunk local end state (h starting from 0)
__device__ float g_H[(size_t)NB * NCHUNK * ND];  // h state at the START of each chunk

// ---------------------------------------------------------------------------
// Kernel 1: per-chunk local recurrence aggregate.
// grid = NB*NCHUNK blocks, 256 threads, 4 channels/thread (float4).
// ---------------------------------------------------------------------------
__global__ void __launch_bounds__(256) k_chunk(const float* __restrict__ x,
                                               const float* __restrict__ A,
                                               const float* __restrict__ B) {
    const int b = blockIdx.x / NCHUNK;
    const int c = blockIdx.x % NCHUNK;
    const int d4 = threadIdx.x * 4;

    const float4 a  = *reinterpret_cast<const float4*>(A + d4);
    const float4 bb = *reinterpret_cast<const float4*>(B + d4);

    const float4* xp = reinterpret_cast<const float4*>(
        x + ((size_t)b * NT + (size_t)c * LCH) * ND + d4);

    float4 h = make_float4(0.f, 0.f, 0.f, 0.f);
    #pragma unroll 8
    for (int t = 0; t < LCH; t++) {
        float4 xv = xp[(size_t)t * (ND / 4)];
        h.x = fmaf(a.x, h.x, bb.x * xv.x);
        h.y = fmaf(a.y, h.y, bb.y * xv.y);
        h.z = fmaf(a.z, h.z, bb.z * xv.z);
        h.w = fmaf(a.w, h.w, bb.w * xv.w);
    }
    *reinterpret_cast<float4*>(&g_S[((size_t)b * NCHUNK + c) * ND + d4]) = h;
}

// ---------------------------------------------------------------------------
// Kernel 2: tiny scan across chunk aggregates per (b, d).
// 8192 threads total. h_start[0] = 0; h_start[c] = A^LCH * h_start[c-1] + S[c-1].
// ---------------------------------------------------------------------------
__global__ void __launch_bounds__(256) k_scan(const float* __restrict__ A) {
    const int idx = blockIdx.x * blockDim.x + threadIdx.x;  // 0 .. NB*ND-1
    const int b = idx / ND;
    const int d = idx % ND;

    const float a = A[d];
    const float a2  = a * a;
    const float a4  = a2 * a2;
    const float a8  = a4 * a4;
    const float a16 = a8 * a8;
    const float a32 = a16 * a16;
    const float aL  = a32 * a32;   // a^64

    float h = 0.f;
    for (int c = 0; c < NCHUNK; c++) {
        const size_t off = ((size_t)b * NCHUNK + c) * ND + d;
        g_H[off] = h;
        h = fmaf(aL, h, g_S[off]);
    }
}

// ---------------------------------------------------------------------------
// Kernel 3: recompute recurrence per chunk from h_start, fused LayerNorm per
// timestep (block owns the full 1024-channel row), streamed output store.
// grid = NB*NCHUNK blocks, 256 threads, 4 channels/thread.
// One __syncthreads() per timestep via double-buffered smem partials +
// redundant 8-way partial read in every thread.
// ---------------------------------------------------------------------------
__global__ void __launch_bounds__(256) k_fuse(const float* __restrict__ x,
                                              const float* __restrict__ A,
                                              const float* __restrict__ B,
                                              const float* __restrict__ C,
                                              const float* __restrict__ D,
                                              const float* __restrict__ G,
                                              const float* __restrict__ Be,
                                              float* __restrict__ out) {
    const int b = blockIdx.x / NCHUNK;
    const int c = blockIdx.x % NCHUNK;
    const int tid = threadIdx.x;
    const int lane = tid & 31;
    const int wid = tid >> 5;
    const int d4 = tid * 4;

    const float4 a  = *reinterpret_cast<const float4*>(A + d4);
    const float4 bb = *reinterpret_cast<const float4*>(B + d4);
    const float4 cc = *reinterpret_cast<const float4*>(C + d4);
    const float4 dd = *reinterpret_cast<const float4*>(D + d4);
    const float4 g  = *reinterpret_cast<const float4*>(G + d4);
    const float4 be = *reinterpret_cast<const float4*>(Be + d4);

    float4 h = *reinterpret_cast<const float4*>(&g_H[((size_t)b * NCHUNK + c) * ND + d4]);

    const size_t base = ((size_t)b * NT + (size_t)c * LCH) * ND + d4;
    const float4* xp = reinterpret_cast<const float4*>(x + base);
    float4* op = reinterpret_cast<float4*>(out + base);

    __shared__ float2 red[2][8];   // double-buffered per-warp (sum, sumsq) partials

    for (int t = 0; t < LCH; t++) {
        float4 xv = __ldcs(&xp[(size_t)t * (ND / 4)]);  // last use of x: evict-first

        h.x = fmaf(a.x, h.x, bb.x * xv.x);
        h.y = fmaf(a.y, h.y, bb.y * xv.y);
        h.z = fmaf(a.z, h.z, bb.z * xv.z);
        h.w = fmaf(a.w, h.w, bb.w * xv.w);

        float4 y;
        y.x = fmaf(cc.x, h.x, dd.x * xv.x);
        y.y = fmaf(cc.y, h.y, dd.y * xv.y);
        y.z = fmaf(cc.z, h.z, dd.z * xv.z);
        y.w = fmaf(cc.w, h.w, dd.w * xv.w);

        float s = (y.x + y.y) + (y.z + y.w);
        float q = fmaf(y.x, y.x, fmaf(y.y, y.y, fmaf(y.z, y.z, y.w * y.w)));

        #pragma unroll
        for (int o = 16; o > 0; o >>= 1) {
            s += __shfl_xor_sync(0xffffffffu, s, o);
            q += __shfl_xor_sync(0xffffffffu, q, o);
        }
        if (lane == 0) red[t & 1][wid] = make_float2(s, q);
        __syncthreads();

        float ts = 0.f, tq = 0.f;
        #pragma unroll
        for (int w = 0; w < 8; w++) {
            float2 p = red[t & 1][w];
            ts += p.x;
            tq += p.y;
        }

        const float mu  = ts * (1.f / ND);
        const float var = fmaf(-mu, mu, tq * (1.f / ND));
        const float r   = rsqrtf(var + EPS);

        float4 o;
        o.x = fmaf((y.x - mu) * r, g.x, be.x);
        o.y = fmaf((y.y - mu) * r, g.y, be.y);
        o.z = fmaf((y.z - mu) * r, g.z, be.z);
        o.w = fmaf((y.w - mu) * r, g.w, be.w);

        __stcs(&op[(size_t)t * (ND / 4)], o);
    }
}

// ---------------------------------------------------------------------------
// Launch: 3 kernels, all graph-capturable, allocation-free.
// Input order per metadata: x, A, B, C, D, gamma, beta. Output: float32 [8,4096,1024].
// ---------------------------------------------------------------------------
extern "C" void kernel_launch(void* const* d_in, const int* in_sizes, int n_in,
                              void* d_out, int out_size) {
    const float* x  = (const float*)d_in[0];
    const float* A  = (const float*)d_in[1];
    const float* B  = (const float*)d_in[2];
    const float* C  = (const float*)d_in[3];
    const float* D  = (const float*)d_in[4];
    const float* G  = (const float*)d_in[5];
    const float* Be = (const float*)d_in[6];
    float* out = (float*)d_out;

    k_chunk<<<NB * NCHUNK, 256>>>(x, A, B);
    k_scan<<<(NB * ND) / 256, 256>>>(A);
    k_fuse<<<NB * NCHUNK, 256>>>(x, A, B, C, D, G, Be, out);
}

// round 6
// speedup vs baseline: 1.1829x; 1.1829x over previous
#include <cuda_runtime.h>

// SimpleSSM: x [8, 4096, 1024] fp32; per-channel diagonal SSM + LayerNorm over dim.
constexpr int NB = 8;
constexpr int NT = 4096;
constexpr int ND = 1024;
constexpr int LCH = 64;                 // timesteps per chunk
constexpr int NCHUNK = NT / LCH;        // 64 chunks per batch
constexpr int NBLK = NB * NCHUNK;       // 512 blocks
constexpr float EPS = 1e-5f;

static_assert(LCH % 4 == 0, "k_fuse processes 4 timesteps per barrier group");

// Scratch (__device__ globals; allocation-free rule).
__device__ float g_S[(size_t)NBLK * ND];  // per-chunk local end state (h from 0)
__device__ float g_H[(size_t)NBLK * ND];  // h state at the START of each chunk

// last-use 128-bit load (legal on sm_100; L2::evict_last is not for .v4.f32)
__device__ __forceinline__ float4 ld_lastuse4(const float4* p) {
    float4 v;
    asm("ld.global.lu.v4.f32 {%0,%1,%2,%3}, [%4];"
        : "=f"(v.x), "=f"(v.y), "=f"(v.z), "=f"(v.w) : "l"(p));
    return v;
}

// ---------------------------------------------------------------------------
// Kernel 1: per-chunk local recurrence aggregate. 512 blocks x 256 threads.
// ---------------------------------------------------------------------------
__global__ void __launch_bounds__(256) k_chunk(const float* __restrict__ x,
                                               const float* __restrict__ A,
                                               const float* __restrict__ B) {
    const int b = blockIdx.x / NCHUNK;
    const int c = blockIdx.x % NCHUNK;
    const int d4 = threadIdx.x * 4;

    const float4 a  = *reinterpret_cast<const float4*>(A + d4);
    const float4 bb = *reinterpret_cast<const float4*>(B + d4);

    const float4* xp = reinterpret_cast<const float4*>(
        x + ((size_t)b * NT + (size_t)c * LCH) * ND + d4);

    float4 h = make_float4(0.f, 0.f, 0.f, 0.f);
    #pragma unroll 8
    for (int t = 0; t < LCH; t++) {
        float4 xv = xp[(size_t)t * (ND / 4)];
        h.x = fmaf(a.x, h.x, bb.x * xv.x);
        h.y = fmaf(a.y, h.y, bb.y * xv.y);
        h.z = fmaf(a.z, h.z, bb.z * xv.z);
        h.w = fmaf(a.w, h.w, bb.w * xv.w);
    }
    *reinterpret_cast<float4*>(&g_S[((size_t)b * NCHUNK + c) * ND + d4]) = h;
}

// ---------------------------------------------------------------------------
// Kernel 2: tiny scan across chunk aggregates per (b, d). 8192 threads.
// ---------------------------------------------------------------------------
__global__ void __launch_bounds__(256) k_scan(const float* __restrict__ A) {
    const int idx = blockIdx.x * blockDim.x + threadIdx.x;
    const int b = idx / ND;
    const int d = idx % ND;

    const float a = A[d];
    float aL = a;
    #pragma unroll
    for (int i = 0; i < 6; i++) aL *= aL;   // a^64

    float h = 0.f;
    for (int c = 0; c < NCHUNK; c++) {
        const size_t off = ((size_t)b * NCHUNK + c) * ND + d;
        g_H[off] = h;
        h = fmaf(aL, h, g_S[off]);
    }
}

// ---------------------------------------------------------------------------
// Kernel 3: recompute recurrence from h_start + fused LayerNorm.
// LIFO chunk mapping: block bid processes chunk NBLK-1-bid, consuming x in
// reverse of k_chunk's streaming order (chases the L2-resident tail).
// 4 timesteps per barrier group; last-use x loads; streaming output stores.
// ---------------------------------------------------------------------------
__global__ void __launch_bounds__(256) k_fuse(const float* __restrict__ x,
                                              const float* __restrict__ A,
                                              const float* __restrict__ B,
                                              const float* __restrict__ C,
                                              const float* __restrict__ D,
                                              const float* __restrict__ G,
                                              const float* __restrict__ Be,
                                              float* __restrict__ out) {
    const int rb = NBLK - 1 - blockIdx.x;   // reversed chunk index
    const int b = rb / NCHUNK;
    const int c = rb % NCHUNK;
    const int tid  = threadIdx.x;
    const int lane = tid & 31;
    const int wid  = tid >> 5;
    const int d4   = tid * 4;

    const float4 a  = *reinterpret_cast<const float4*>(A + d4);
    const float4 bb = *reinterpret_cast<const float4*>(B + d4);
    const float4 cc = *reinterpret_cast<const float4*>(C + d4);
    const float4 dd = *reinterpret_cast<const float4*>(D + d4);
    const float4 g4 = *reinterpret_cast<const float4*>(G + d4);
    const float4 be = *reinterpret_cast<const float4*>(Be + d4);

    float4 h = *reinterpret_cast<const float4*>(&g_H[((size_t)b * NCHUNK + c) * ND + d4]);

    const size_t base = ((size_t)b * NT + (size_t)c * LCH) * ND + d4;
    const float4* xp = reinterpret_cast<const float4*>(x + base);
    float4* op = reinterpret_cast<float4*>(out + base);

    __shared__ float2 red[2][4][8];   // [parity][timestep j][warp] (sum, sumsq)
    __shared__ float2 mur[2][4];      // [parity][timestep j] (mu, rstd)

    for (int gq = 0; gq < LCH / 4; gq++) {
        const int par = gq & 1;

        // 4 independent x loads in flight (last use)
        float4 xv[4];
        #pragma unroll
        for (int j = 0; j < 4; j++)
            xv[j] = ld_lastuse4(&xp[(size_t)(gq * 4 + j) * (ND / 4)]);

        // sequential recurrence + y for the 4 timesteps
        float4 y[4];
        #pragma unroll
        for (int j = 0; j < 4; j++) {
            h.x = fmaf(a.x, h.x, bb.x * xv[j].x);
            h.y = fmaf(a.y, h.y, bb.y * xv[j].y);
            h.z = fmaf(a.z, h.z, bb.z * xv[j].z);
            h.w = fmaf(a.w, h.w, bb.w * xv[j].w);
            y[j].x = fmaf(cc.x, h.x, dd.x * xv[j].x);
            y[j].y = fmaf(cc.y, h.y, dd.y * xv[j].y);
            y[j].z = fmaf(cc.z, h.z, dd.z * xv[j].z);
            y[j].w = fmaf(cc.w, h.w, dd.w * xv[j].w);
        }

        // per-thread (sum, sumsq), warp reduce (4 timesteps interleaved)
        float s[4], q[4];
        #pragma unroll
        for (int j = 0; j < 4; j++) {
            s[j] = (y[j].x + y[j].y) + (y[j].z + y[j].w);
            q[j] = fmaf(y[j].x, y[j].x,
                   fmaf(y[j].y, y[j].y,
                   fmaf(y[j].z, y[j].z, y[j].w * y[j].w)));
        }
        #pragma unroll
        for (int o = 16; o > 0; o >>= 1) {
            #pragma unroll
            for (int j = 0; j < 4; j++) {
                s[j] += __shfl_xor_sync(0xffffffffu, s[j], o);
                q[j] += __shfl_xor_sync(0xffffffffu, q[j], o);
            }
        }
        if (lane == 0) {
            #pragma unroll
            for (int j = 0; j < 4; j++)
                red[par][j][wid] = make_float2(s[j], q[j]);
        }
        __syncthreads();

        // warp 0 reduces across the 8 warps for all 4 timesteps at once
        if (wid == 0) {
            const int j = lane >> 3;   // 0..3
            const int w = lane & 7;    // 0..7
            float2 p = red[par][j][w];
            #pragma unroll
            for (int o = 4; o > 0; o >>= 1) {
                p.x += __shfl_xor_sync(0xffffffffu, p.x, o);
                p.y += __shfl_xor_sync(0xffffffffu, p.y, o);
            }
            if (w == 0) {
                const float mu  = p.x * (1.f / ND);
                const float var = fmaf(-mu, mu, p.y * (1.f / ND));
                mur[par][j] = make_float2(mu, rsqrtf(var + EPS));
            }
        }
        __syncthreads();

        // normalize + streamed stores (4 in flight)
        #pragma unroll
        for (int j = 0; j < 4; j++) {
            const float2 mr = mur[par][j];
            float4 o;
            o.x = fmaf((y[j].x - mr.x) * mr.y, g4.x, be.x);
            o.y = fmaf((y[j].y - mr.x) * mr.y, g4.y, be.y);
            o.z = fmaf((y[j].z - mr.x) * mr.y, g4.z, be.z);
            o.w = fmaf((y[j].w - mr.x) * mr.y, g4.w, be.w);
            __stcs(&op[(size_t)(gq * 4 + j) * (ND / 4)], o);
        }
    }
}

extern "C" void kernel_launch(void* const* d_in, const int* in_sizes, int n_in,
                              void* d_out, int out_size) {
    const float* x  = (const float*)d_in[0];
    const float* A  = (const float*)d_in[1];
    const float* B  = (const float*)d_in[2];
    const float* C  = (const float*)d_in[3];
    const float* D  = (const float*)d_in[4];
    const float* G  = (const float*)d_in[5];
    const float* Be = (const float*)d_in[6];
    float* out = (float*)d_out;

    k_chunk<<<NB * NCHUNK, 256>>>(x, A, B);
    k_scan<<<(NB * ND) / 256, 256>>>(A);
    k_fuse<<<NB * NCHUNK, 256>>>(x, A, B, C, D, G, Be, out);
}

// round 7
// speedup vs baseline: 1.4610x; 1.2351x over previous
#include <cuda_runtime.h>

// SimpleSSM: x [8, 4096, 1024] fp32; per-channel diagonal SSM + LayerNorm over dim.
constexpr int NB = 8;
constexpr int NT = 4096;
constexpr int ND = 1024;
constexpr int LCH = 64;                 // timesteps per chunk
constexpr int NCHUNK = NT / LCH;        // 64 chunks per batch
constexpr int NBLK = NB * NCHUNK;       // 512 blocks (all co-resident at 4 blocks/SM)
constexpr float EPS = 1e-5f;

// Scratch (__device__ globals; allocation-free rule).
__device__ float g_S[(size_t)NBLK * ND];   // per-chunk local end state (h from 0)
__device__ unsigned int g_cnt;             // grid-barrier arrival counter

__global__ void k_reset() {
    if (threadIdx.x == 0 && blockIdx.x == 0) g_cnt = 0u;
}

__device__ __forceinline__ unsigned int ld_cnt(const unsigned int* p) {
    unsigned int v;
    asm volatile("ld.global.cg.b32 %0, [%1];" : "=r"(v) : "l"(p));
    return v;
}
__device__ __forceinline__ float4 ld_lastuse4(const float4* p) {
    float4 v;
    asm("ld.global.lu.v4.f32 {%0,%1,%2,%3}, [%4];"
        : "=f"(v.x), "=f"(v.y), "=f"(v.z), "=f"(v.w) : "l"(p));
    return v;
}
__device__ __forceinline__ float4 ldcg4(const float* p) {
    return __ldcg(reinterpret_cast<const float4*>(p));
}

// __launch_bounds__(256, 4): regs capped at 64 -> 4 blocks/SM guaranteed ->
// all 512 blocks resident in wave 1 -> the global barrier cannot starve.
__global__ void __launch_bounds__(256, 4) k_ssm(const float* __restrict__ x,
                                                const float* __restrict__ A,
                                                const float* __restrict__ B,
                                                const float* __restrict__ C,
                                                const float* __restrict__ D,
                                                const float* __restrict__ G,
                                                const float* __restrict__ Be,
                                                float* __restrict__ out) {
    const int b = blockIdx.x / NCHUNK;
    const int c = blockIdx.x % NCHUNK;
    const int tid  = threadIdx.x;
    const int lane = tid & 31;
    const int wid  = tid >> 5;
    const int d4   = tid * 4;

    const float4 a  = *reinterpret_cast<const float4*>(A + d4);
    const float4 bb = *reinterpret_cast<const float4*>(B + d4);

    const size_t base = ((size_t)b * NT + (size_t)c * LCH) * ND + d4;
    const float4* xp = reinterpret_cast<const float4*>(x + base);

    // ---- Phase 1: local chunk aggregate (h starting from 0) ----
    float4 S = make_float4(0.f, 0.f, 0.f, 0.f);
    #pragma unroll 8
    for (int t = 0; t < LCH; t++) {
        float4 xv = xp[(size_t)t * (ND / 4)];
        S.x = fmaf(a.x, S.x, bb.x * xv.x);
        S.y = fmaf(a.y, S.y, bb.y * xv.y);
        S.z = fmaf(a.z, S.z, bb.z * xv.z);
        S.w = fmaf(a.w, S.w, bb.w * xv.w);
    }
    *reinterpret_cast<float4*>(&g_S[(size_t)blockIdx.x * ND + d4]) = S;
    __syncthreads();

    // ---- Global barrier: wait until every block has published its aggregate ----
    if (tid == 0) {
        __threadfence();
        atomicAdd(&g_cnt, 1u);
        while (ld_cnt(&g_cnt) < (unsigned int)NBLK) __nanosleep(64);
    }
    __syncthreads();
    __threadfence();   // acquire: order the spin before the g_S reads below

    // ---- Phase 2: h_start = sum_{k<c} aL^(c-1-k) * S_k (L2-hot, independent loads) ----
    float4 aL = a;
    #pragma unroll
    for (int i = 0; i < 6; i++) {        // a^64
        aL.x *= aL.x; aL.y *= aL.y; aL.z *= aL.z; aL.w *= aL.w;
    }
    float4 h    = make_float4(0.f, 0.f, 0.f, 0.f);
    float4 coef = make_float4(1.f, 1.f, 1.f, 1.f);
    for (int k = c - 1; k >= 0; k--) {
        float4 Sk = ldcg4(&g_S[((size_t)b * NCHUNK + k) * ND + d4]);
        h.x = fmaf(coef.x, Sk.x, h.x);
        h.y = fmaf(coef.y, Sk.y, h.y);
        h.z = fmaf(coef.z, Sk.z, h.z);
        h.w = fmaf(coef.w, Sk.w, h.w);
        coef.x *= aL.x; coef.y *= aL.y; coef.z *= aL.z; coef.w *= aL.w;
    }

    // ---- Phase 3: re-run recurrence from h_start + fused LayerNorm ----
    // Same chunk of x as phase 1 -> still L2-resident -> LTS-rate reads.
    const float4 cc = *reinterpret_cast<const float4*>(C + d4);
    const float4 dd = *reinterpret_cast<const float4*>(D + d4);

    float4* op = reinterpret_cast<float4*>(out + base);

    __shared__ float2 red[2][4][8];   // [parity][timestep j][warp] (sum, sumsq)
    __shared__ float2 mur[2][4];      // [parity][timestep j] (mu, rstd)

    for (int gq = 0; gq < LCH / 4; gq++) {
        const int par = gq & 1;

        // 4 independent x loads in flight (last use)
        float4 xv[4];
        #pragma unroll
        for (int j = 0; j < 4; j++)
            xv[j] = ld_lastuse4(&xp[(size_t)(gq * 4 + j) * (ND / 4)]);

        // sequential recurrence + y for the 4 timesteps
        float4 y[4];
        #pragma unroll
        for (int j = 0; j < 4; j++) {
            h.x = fmaf(a.x, h.x, bb.x * xv[j].x);
            h.y = fmaf(a.y, h.y, bb.y * xv[j].y);
            h.z = fmaf(a.z, h.z, bb.z * xv[j].z);
            h.w = fmaf(a.w, h.w, bb.w * xv[j].w);
            y[j].x = fmaf(cc.x, h.x, dd.x * xv[j].x);
            y[j].y = fmaf(cc.y, h.y, dd.y * xv[j].y);
            y[j].z = fmaf(cc.z, h.z, dd.z * xv[j].z);
            y[j].w = fmaf(cc.w, h.w, dd.w * xv[j].w);
        }

        // per-thread (sum, sumsq), warp reduce (4 timesteps interleaved)
        float s[4], q[4];
        #pragma unroll
        for (int j = 0; j < 4; j++) {
            s[j] = (y[j].x + y[j].y) + (y[j].z + y[j].w);
            q[j] = fmaf(y[j].x, y[j].x,
                   fmaf(y[j].y, y[j].y,
                   fmaf(y[j].z, y[j].z, y[j].w * y[j].w)));
        }
        #pragma unroll
        for (int o = 16; o > 0; o >>= 1) {
            #pragma unroll
            for (int j = 0; j < 4; j++) {
                s[j] += __shfl_xor_sync(0xffffffffu, s[j], o);
                q[j] += __shfl_xor_sync(0xffffffffu, q[j], o);
            }
        }
        if (lane == 0) {
            #pragma unroll
            for (int j = 0; j < 4; j++)
                red[par][j][wid] = make_float2(s[j], q[j]);
        }
        __syncthreads();

        // warp 0 reduces across the 8 warps for all 4 timesteps at once
        if (wid == 0) {
            const int j = lane >> 3;   // 0..3
            const int w = lane & 7;    // 0..7
            float2 p = red[par][j][w];
            #pragma unroll
            for (int o = 4; o > 0; o >>= 1) {
                p.x += __shfl_xor_sync(0xffffffffu, p.x, o);
                p.y += __shfl_xor_sync(0xffffffffu, p.y, o);
            }
            if (w == 0) {
                const float mu  = p.x * (1.f / ND);
                const float var = fmaf(-mu, mu, p.y * (1.f / ND));
                mur[par][j] = make_float2(mu, rsqrtf(var + EPS));
            }
        }
        __syncthreads();

        // normalize + streamed stores; gamma/beta reloaded via __ldg (L1-hot)
        // to stay under the 64-register occupancy cap.
        const float4 g4 = __ldg(reinterpret_cast<const float4*>(G + d4));
        const float4 be = __ldg(reinterpret_cast<const float4*>(Be + d4));
        #pragma unroll
        for (int j = 0; j < 4; j++) {
            const float2 mr = mur[par][j];
            float4 o;
            o.x = fmaf((y[j].x - mr.x) * mr.y, g4.x, be.x);
            o.y = fmaf((y[j].y - mr.x) * mr.y, g4.y, be.y);
            o.z = fmaf((y[j].z - mr.x) * mr.y, g4.z, be.z);
            o.w = fmaf((y[j].w - mr.x) * mr.y, g4.w, be.w);
            __stcs(&op[(size_t)(gq * 4 + j) * (ND / 4)], o);
        }
    }
}

extern "C" void kernel_launch(void* const* d_in, const int* in_sizes, int n_in,
                              void* d_out, int out_size) {
    const float* x  = (const float*)d_in[0];
    const float* A  = (const float*)d_in[1];
    const float* B  = (const float*)d_in[2];
    const float* C  = (const float*)d_in[3];
    const float* D  = (const float*)d_in[4];
    const float* G  = (const float*)d_in[5];
    const float* Be = (const float*)d_in[6];
    float* out = (float*)d_out;

    k_reset<<<1, 32>>>();
    k_ssm<<<NBLK, 256>>>(x, A, B, C, D, G, Be, out);
}